// round 3
// baseline (speedup 1.0000x reference)
#include <cuda_runtime.h>
#include <cstdint>

static constexpr int   kVocab   = 128000;
static constexpr int   kTopK    = 50;
static constexpr float kTopP    = 0.9f;
static constexpr float kNeg     = -1000000000.0f;
static constexpr int   kThreads = 1024;
static constexpr int   kCap     = 4096;   // candidate buffer capacity (shared)

// Order-preserving float -> uint32 key (monotone increasing).
__device__ __forceinline__ unsigned f2key(float f) {
    unsigned b = __float_as_uint(f);
    return (b & 0x80000000u) ? ~b : (b | 0x80000000u);
}
__device__ __forceinline__ float key2f(unsigned k) {
    unsigned b = (k & 0x80000000u) ? (k & 0x7FFFFFFFu) : ~k;
    return __uint_as_float(b);
}

// Warp-aggregated candidate push: one atomicAdd per warp per component.
__device__ __forceinline__ void push_cand_warp(
    float v, int idx, float T, int lane,
    int* s_cnt, unsigned long long* s_cand)
{
    bool pred = v > T;
    unsigned m = __ballot_sync(0xffffffffu, pred);
    if (m) {                       // warp-uniform branch
        int leader = __ffs(m) - 1;
        int base = 0;
        if (lane == leader) base = atomicAdd(s_cnt, __popc(m));
        base = __shfl_sync(0xffffffffu, base, leader);
        if (pred) {
            int p = base + __popc(m & ((1u << lane) - 1u));
            if (p < kCap)
                s_cand[p] = ((unsigned long long)f2key(v) << 32) | (unsigned)idx;
        }
    }
}

__global__ void __launch_bounds__(kThreads, 2)
topk_topp_kernel(const float* __restrict__ in, float* __restrict__ out) {
    __shared__ unsigned long long s_cand[kCap];
    __shared__ float s_wm[32];       // sorted (ascending) warp maxima of samples
    __shared__ float s_ex[kTopK];    // exp(v - max) for top tokens
    __shared__ int   s_cnt;
    __shared__ float s_T;
    __shared__ int   s_k;

    const int row  = blockIdx.x;
    const float* rin  = in  + (long long)row * kVocab;
    float*       rout = out + (long long)row * kVocab;
    const int tid  = threadIdx.x;
    const int lane = tid & 31;
    const int wid  = tid >> 5;

    // ---------------- Phase 0: sample-based threshold estimate ----------------
    float sv = __ldcs(&rin[tid * (kVocab / kThreads)]);
#pragma unroll
    for (int o = 16; o > 0; o >>= 1)
        sv = fmaxf(sv, __shfl_xor_sync(0xffffffffu, sv, o));
    if (lane == 0) s_wm[wid] = sv;
    __syncthreads();
    if (wid == 0) {
        float x = s_wm[lane];
#pragma unroll
        for (int k = 2; k <= 32; k <<= 1) {
#pragma unroll
            for (int j = k >> 1; j > 0; j >>= 1) {
                float y     = __shfl_xor_sync(0xffffffffu, x, j);
                bool  up    = ((lane & k) == 0);
                bool  lower = ((lane & j) == 0);
                x = (up == lower) ? fminf(x, y) : fmaxf(x, y);
            }
        }
        s_wm[lane] = x;  // ascending
    }
    __syncthreads();

    // ---------------- Phase 1: fused NEG-fill + candidate collection ----------------
    const float4* rin4  = reinterpret_cast<const float4*>(rin);
    float4*       rout4 = reinterpret_cast<float4*>(rout);
    const int n4 = kVocab / 4;
    const float4 neg4 = make_float4(kNeg, kNeg, kNeg, kNeg);

    int rank = 7;  // 8th-largest warp max; expected exceedance ~1000-2000
    if (tid == 0) { s_cnt = 0; s_T = s_wm[31 - rank]; }
    __syncthreads();
    float T = s_T;

#pragma unroll 2
    for (int i = tid; i < n4; i += kThreads) {
        float4 x = __ldcs(&rin4[i]);
        __stcs(&rout4[i], neg4);  // fill (kept slots overwritten in phase 4)
        push_cand_warp(x.x, 4 * i,     T, lane, &s_cnt, s_cand);
        push_cand_warp(x.y, 4 * i + 1, T, lane, &s_cnt, s_cand);
        push_cand_warp(x.z, 4 * i + 2, T, lane, &s_cnt, s_cand);
        push_cand_warp(x.w, 4 * i + 3, T, lane, &s_cnt, s_cand);
    }
    __syncthreads();
    int cnt = s_cnt;

    // Retry ladder (essentially never taken for continuous data).
    for (int attempt = 0; attempt < 4 && (cnt < kTopK || cnt > kCap); ++attempt) {
        if (cnt < kTopK) rank = (rank < 31) ? (rank * 2 + 1) : 31;  // lower threshold
        else             rank = rank >> 1;                           // raise threshold
        __syncthreads();
        if (tid == 0) { s_cnt = 0; s_T = s_wm[31 - rank]; }
        __syncthreads();
        T = s_T;
        for (int i = tid; i < n4; i += kThreads) {
            float4 x = __ldcs(&rin4[i]);
            push_cand_warp(x.x, 4 * i,     T, lane, &s_cnt, s_cand);
            push_cand_warp(x.y, 4 * i + 1, T, lane, &s_cnt, s_cand);
            push_cand_warp(x.z, 4 * i + 2, T, lane, &s_cnt, s_cand);
            push_cand_warp(x.w, 4 * i + 3, T, lane, &s_cnt, s_cand);
        }
        __syncthreads();
        cnt = s_cnt;
    }

    int n = cnt < kCap ? cnt : kCap;

    // ---------------- Phase 2: bitonic sort candidates (descending) ----------------
    int npad = 64;
    while (npad < n) npad <<= 1;
    for (int i = n + tid; i < npad; i += kThreads) s_cand[i] = 0ull;  // key 0 < any real key
    __syncthreads();

    for (int k = 2; k <= npad; k <<= 1) {
        for (int j = k >> 1; j > 0; j >>= 1) {
            for (int i = tid; i < npad; i += kThreads) {
                int p = i ^ j;
                if (p > i) {
                    unsigned long long a = s_cand[i];
                    unsigned long long b = s_cand[p];
                    bool desc = ((i & k) == 0);
                    if (desc ? (a < b) : (a > b)) { s_cand[i] = b; s_cand[p] = a; }
                }
            }
            __syncthreads();
        }
    }

    // ---------------- Phase 3: softmax cum-prob over top-50, find kept count ----------------
    if (tid == 0) {
        int lim = (n < kTopK) ? n : kTopK;
        int kk = 0;
        if (lim > 0) {
            float m = key2f((unsigned)(s_cand[0] >> 32));
            float Z = 0.f;
            for (int j = 0; j < lim; ++j) {
                float vj = key2f((unsigned)(s_cand[j] >> 32));
                float e  = expf(vj - m);
                s_ex[j]  = e;
                Z += e;
            }
            // keep token j iff j==0 or cum_{j-1} <= p
            float cum = 0.f;
            for (int j = 0; j < lim; ++j) {
                if (j > 0 && cum > kTopP) break;
                kk = j + 1;
                cum += s_ex[j] / Z;
            }
        }
        s_k = kk;
    }
    __syncthreads();

    // ---------------- Phase 4: scatter kept values over the NEG fill ----------------
    if (tid < s_k) {
        unsigned long long c = s_cand[tid];
        int idx = (int)(c & 0xFFFFFFFFu);
        rout[idx] = key2f((unsigned)(c >> 32));
    }
}

extern "C" void kernel_launch(void* const* d_in, const int* in_sizes, int n_in,
                              void* d_out, int out_size) {
    const float* in = (const float*)d_in[0];
    float* out = (float*)d_out;
    int rows = in_sizes[0] / kVocab;
    topk_topp_kernel<<<rows, kThreads>>>(in, out);
}

// round 4
// speedup vs baseline: 1.2474x; 1.2474x over previous
#include <cuda_runtime.h>
#include <cstdint>

static constexpr int   kVocab   = 128000;
static constexpr int   kTopK    = 50;
static constexpr float kTopP    = 0.9f;
static constexpr float kNeg     = -1000000000.0f;
static constexpr int   kThreads = 1024;
static constexpr int   kWCap    = 64;            // per-warp candidate slots
static constexpr int   kCap     = 32 * kWCap;    // 2048 total (fixed sort size)

// Order-preserving float -> uint32 key (monotone increasing, >0 for any float).
__device__ __forceinline__ unsigned f2key(float f) {
    unsigned b = __float_as_uint(f);
    return (b & 0x80000000u) ? ~b : (b | 0x80000000u);
}
__device__ __forceinline__ float key2f(unsigned k) {
    unsigned b = (k & 0x80000000u) ? (k & 0x7FFFFFFFu) : ~k;
    return __uint_as_float(b);
}

__global__ void __launch_bounds__(kThreads, 2)
topk_topp_kernel(const float* __restrict__ in, float* __restrict__ out) {
    __shared__ unsigned long long s_cand[kCap];  // per-warp segments of kWCap
    __shared__ int   s_wcnt[32];
    __shared__ float s_wm[32];     // sorted (ascending) warp maxima of samples
    __shared__ float s_ex[kTopK];
    __shared__ float s_T;
    __shared__ int   s_total;
    __shared__ int   s_ovf;
    __shared__ int   s_k;

    const int row  = blockIdx.x;
    const float* rin  = in  + (long long)row * kVocab;
    float*       rout = out + (long long)row * kVocab;
    const int tid  = threadIdx.x;
    const int lane = tid & 31;
    const int wid  = tid >> 5;

    // ---------------- Phase 0: sample-based threshold estimate ----------------
    float sv = __ldcs(&rin[tid * (kVocab / kThreads)]);
#pragma unroll
    for (int o = 16; o > 0; o >>= 1)
        sv = fmaxf(sv, __shfl_xor_sync(0xffffffffu, sv, o));
    if (lane == 0) s_wm[wid] = sv;
    __syncthreads();
    if (wid == 0) {
        float x = s_wm[lane];
#pragma unroll
        for (int k = 2; k <= 32; k <<= 1) {
#pragma unroll
            for (int j = k >> 1; j > 0; j >>= 1) {
                float y     = __shfl_xor_sync(0xffffffffu, x, j);
                bool  up    = ((lane & k) == 0);
                bool  lower = ((lane & j) == 0);
                x = (up == lower) ? fminf(x, y) : fmaxf(x, y);
            }
        }
        s_wm[lane] = x;  // ascending
    }

    // Zero candidate buffer + counters (zeros sort below any real key).
    for (int i = tid; i < kCap; i += kThreads) s_cand[i] = 0ull;
    if (tid < 32) s_wcnt[tid] = 0;

    int rank = 5;  // 6th-largest warp max; expected exceedance ~750
    __syncthreads();
    if (tid == 0) s_T = s_wm[31 - rank];
    __syncthreads();
    float T = s_T;

    // ---------------- Phase 1: fused NEG-fill + candidate collection ----------------
    const float4* rin4  = reinterpret_cast<const float4*>(rin);
    float4*       rout4 = reinterpret_cast<float4*>(rout);
    const int n4 = kVocab / 4;
    const float4 neg4 = make_float4(kNeg, kNeg, kNeg, kNeg);

#define PUSH4(v, base)                                                            \
    {                                                                             \
        if (v.x > T) { int p = atomicAdd(&s_wcnt[wid], 1);                        \
            if (p < kWCap) s_cand[wid * kWCap + p] =                              \
                ((unsigned long long)f2key(v.x) << 32) | (unsigned)(base); }      \
        if (v.y > T) { int p = atomicAdd(&s_wcnt[wid], 1);                        \
            if (p < kWCap) s_cand[wid * kWCap + p] =                              \
                ((unsigned long long)f2key(v.y) << 32) | (unsigned)(base + 1); }  \
        if (v.z > T) { int p = atomicAdd(&s_wcnt[wid], 1);                        \
            if (p < kWCap) s_cand[wid * kWCap + p] =                              \
                ((unsigned long long)f2key(v.z) << 32) | (unsigned)(base + 2); }  \
        if (v.w > T) { int p = atomicAdd(&s_wcnt[wid], 1);                        \
            if (p < kWCap) s_cand[wid * kWCap + p] =                              \
                ((unsigned long long)f2key(v.w) << 32) | (unsigned)(base + 3); }  \
    }

    for (int i = tid; i < n4; i += 2 * kThreads) {
        const int i2 = i + kThreads;
        const bool h2 = i2 < n4;
        float4 a = __ldcs(&rin4[i]);
        float4 b;
        if (h2) b = __ldcs(&rin4[i2]);
        __stcs(&rout4[i], neg4);
        if (h2) __stcs(&rout4[i2], neg4);
        float ma = fmaxf(fmaxf(a.x, a.y), fmaxf(a.z, a.w));
        if (ma > T) PUSH4(a, 4 * i);                       // rare
        if (h2) {
            float mb = fmaxf(fmaxf(b.x, b.y), fmaxf(b.z, b.w));
            if (mb > T) PUSH4(b, 4 * i2);                  // rare
        }
    }
    __syncthreads();

    // Count + overflow check (warp 0).
    if (wid == 0) {
        int c = s_wcnt[lane];
        int ov = __any_sync(0xffffffffu, c > kWCap) ? 1 : 0;
        int t = c;
#pragma unroll
        for (int o = 16; o > 0; o >>= 1) t += __shfl_xor_sync(0xffffffffu, t, o);
        if (lane == 0) { s_total = t; s_ovf = ov; }
    }
    __syncthreads();
    int total = s_total, ovf = s_ovf;

    // Retry ladder (rare: threshold too high/low or per-warp overflow).
    for (int attempt = 0; attempt < 4 && (total < kTopK || ovf); ++attempt) {
        if (ovf)              rank = rank >> 1;                       // raise threshold
        else                  rank = (rank < 31) ? (rank * 2 + 1) : 31; // lower threshold
        __syncthreads();
        for (int i = tid; i < kCap; i += kThreads) s_cand[i] = 0ull;
        if (tid < 32) s_wcnt[tid] = 0;
        if (tid == 0) s_T = s_wm[31 - rank];
        __syncthreads();
        T = s_T;
        for (int i = tid; i < n4; i += 2 * kThreads) {
            const int i2 = i + kThreads;
            const bool h2 = i2 < n4;
            float4 a = __ldcs(&rin4[i]);
            float4 b;
            if (h2) b = __ldcs(&rin4[i2]);
            float ma = fmaxf(fmaxf(a.x, a.y), fmaxf(a.z, a.w));
            if (ma > T) PUSH4(a, 4 * i);
            if (h2) {
                float mb = fmaxf(fmaxf(b.x, b.y), fmaxf(b.z, b.w));
                if (mb > T) PUSH4(b, 4 * i2);
            }
        }
        __syncthreads();
        if (wid == 0) {
            int c = s_wcnt[lane];
            int ov = __any_sync(0xffffffffu, c > kWCap) ? 1 : 0;
            int t = c;
#pragma unroll
            for (int o = 16; o > 0; o >>= 1) t += __shfl_xor_sync(0xffffffffu, t, o);
            if (lane == 0) { s_total = t; s_ovf = ov; }
        }
        __syncthreads();
        total = s_total; ovf = s_ovf;
    }
#undef PUSH4

    // ---------------- Phase 2: bitonic sort (descending) over fixed kCap ----------------
    // Zeros (empty slots) have key 0 < any real key, so they sink to the bottom.
    for (int k = 2; k <= kCap; k <<= 1) {
        for (int j = k >> 1; j > 0; j >>= 1) {
#pragma unroll 1
            for (int i = tid; i < kCap; i += kThreads) {
                int p = i ^ j;
                if (p > i) {
                    unsigned long long a = s_cand[i];
                    unsigned long long b = s_cand[p];
                    bool desc = ((i & k) == 0);
                    if (desc ? (a < b) : (a > b)) { s_cand[i] = b; s_cand[p] = a; }
                }
            }
            __syncthreads();
        }
    }

    // ---------------- Phase 3: softmax cum-prob over top-50, find kept count ----------------
    if (tid == 0) {
        int lim = (total < kTopK) ? total : kTopK;
        int kk = 0;
        if (lim > 0) {
            float m = key2f((unsigned)(s_cand[0] >> 32));
            float Z = 0.f;
            for (int j = 0; j < lim; ++j) {
                float vj = key2f((unsigned)(s_cand[j] >> 32));
                float e  = expf(vj - m);
                s_ex[j]  = e;
                Z += e;
            }
            float cum = 0.f;
            for (int j = 0; j < lim; ++j) {
                if (j > 0 && cum > kTopP) break;
                kk = j + 1;
                cum += s_ex[j] / Z;
            }
        }
        s_k = kk;
    }
    __syncthreads();

    // ---------------- Phase 4: scatter kept values over the NEG fill ----------------
    if (tid < s_k) {
        unsigned long long c = s_cand[tid];
        int idx = (int)(c & 0xFFFFFFFFu);
        rout[idx] = key2f((unsigned)(c >> 32));
    }
}

extern "C" void kernel_launch(void* const* d_in, const int* in_sizes, int n_in,
                              void* d_out, int out_size) {
    const float* in = (const float*)d_in[0];
    float* out = (float*)d_out;
    int rows = in_sizes[0] / kVocab;
    topk_topp_kernel<<<rows, kThreads>>>(in, out);
}

// round 5
// speedup vs baseline: 1.3692x; 1.0977x over previous
#include <cuda_runtime.h>
#include <cstdint>

static constexpr int   kVocab   = 128000;
static constexpr int   kTopK    = 50;
static constexpr float kTopP    = 0.9f;
static constexpr float kNeg     = -1000000000.0f;
static constexpr int   kThreads = 1024;
static constexpr int   kWCap    = 64;            // per-warp candidate slots
static constexpr int   kCap     = 32 * kWCap;    // 2048 max candidates

// Order-preserving float -> uint32 key (monotone increasing, >0 for any float).
__device__ __forceinline__ unsigned f2key(float f) {
    unsigned b = __float_as_uint(f);
    return (b & 0x80000000u) ? ~b : (b | 0x80000000u);
}
__device__ __forceinline__ float key2f(unsigned k) {
    unsigned b = (k & 0x80000000u) ? (k & 0x7FFFFFFFu) : ~k;
    return __uint_as_float(b);
}
__device__ __forceinline__ unsigned long long shfl_xor64(unsigned long long v, int j) {
    unsigned lo = __shfl_xor_sync(0xffffffffu, (unsigned)v, j);
    unsigned hi = __shfl_xor_sync(0xffffffffu, (unsigned)(v >> 32), j);
    return ((unsigned long long)hi << 32) | lo;
}

__global__ void __launch_bounds__(kThreads, 2)
topk_topp_kernel(const float* __restrict__ in, float* __restrict__ out) {
    __shared__ unsigned long long s_cand[kCap];    // per-warp segments (gaps ok)
    __shared__ unsigned long long s_sorted[kCap];  // compacted + sorted
    __shared__ int   s_wcnt[32];
    __shared__ int   s_woff[32];
    __shared__ float s_wm[32];     // sorted (ascending) warp maxima of samples
    __shared__ float s_ex[kTopK];
    __shared__ float s_T;
    __shared__ int   s_total;
    __shared__ int   s_ovf;
    __shared__ int   s_k;

    const int row  = blockIdx.x;
    const float* rin  = in  + (long long)row * kVocab;
    float*       rout = out + (long long)row * kVocab;
    const int tid  = threadIdx.x;
    const int lane = tid & 31;
    const int wid  = tid >> 5;

    // ---------------- Phase 0: sample-based threshold estimate ----------------
    float sv = __ldcs(&rin[tid * (kVocab / kThreads)]);
#pragma unroll
    for (int o = 16; o > 0; o >>= 1)
        sv = fmaxf(sv, __shfl_xor_sync(0xffffffffu, sv, o));
    if (lane == 0) s_wm[wid] = sv;
    __syncthreads();
    if (wid == 0) {
        float x = s_wm[lane];
#pragma unroll
        for (int k = 2; k <= 32; k <<= 1) {
#pragma unroll
            for (int j = k >> 1; j > 0; j >>= 1) {
                float y     = __shfl_xor_sync(0xffffffffu, x, j);
                bool  up    = ((lane & k) == 0);
                bool  lower = ((lane & j) == 0);
                x = (up == lower) ? fminf(x, y) : fmaxf(x, y);
            }
        }
        s_wm[lane] = x;  // ascending
    }
    if (tid < 32) s_wcnt[tid] = 0;

    int rank = 5;  // 6th-largest warp max; expected exceedance ~750
    __syncthreads();
    if (tid == 0) s_T = s_wm[31 - rank];
    __syncthreads();
    float T = s_T;

    // ---------------- Phase 1: fused NEG-fill + candidate collection ----------------
    const float4* rin4  = reinterpret_cast<const float4*>(rin);
    float4*       rout4 = reinterpret_cast<float4*>(rout);
    const int n4 = kVocab / 4;
    const float4 neg4 = make_float4(kNeg, kNeg, kNeg, kNeg);

#define PUSH4(v, base)                                                            \
    {                                                                             \
        if (v.x > T) { int p = atomicAdd(&s_wcnt[wid], 1);                        \
            if (p < kWCap) s_cand[wid * kWCap + p] =                              \
                ((unsigned long long)f2key(v.x) << 32) | (unsigned)(base); }      \
        if (v.y > T) { int p = atomicAdd(&s_wcnt[wid], 1);                        \
            if (p < kWCap) s_cand[wid * kWCap + p] =                              \
                ((unsigned long long)f2key(v.y) << 32) | (unsigned)(base + 1); }  \
        if (v.z > T) { int p = atomicAdd(&s_wcnt[wid], 1);                        \
            if (p < kWCap) s_cand[wid * kWCap + p] =                              \
                ((unsigned long long)f2key(v.z) << 32) | (unsigned)(base + 2); }  \
        if (v.w > T) { int p = atomicAdd(&s_wcnt[wid], 1);                        \
            if (p < kWCap) s_cand[wid * kWCap + p] =                              \
                ((unsigned long long)f2key(v.w) << 32) | (unsigned)(base + 3); }  \
    }

    // Batch-4 stream: 4 independent loads in flight per thread.
    for (int i0 = tid; i0 < n4; i0 += 4 * kThreads) {
        const int i1 = i0 + kThreads, i2 = i0 + 2 * kThreads, i3 = i0 + 3 * kThreads;
        const bool h1 = i1 < n4, h2 = i2 < n4, h3 = i3 < n4;
        float4 a = __ldcs(&rin4[i0]);
        float4 b, c, d;
        if (h1) b = __ldcs(&rin4[i1]);
        if (h2) c = __ldcs(&rin4[i2]);
        if (h3) d = __ldcs(&rin4[i3]);
        __stcs(&rout4[i0], neg4);
        if (h1) __stcs(&rout4[i1], neg4);
        if (h2) __stcs(&rout4[i2], neg4);
        if (h3) __stcs(&rout4[i3], neg4);
        if (fmaxf(fmaxf(a.x, a.y), fmaxf(a.z, a.w)) > T) PUSH4(a, 4 * i0);
        if (h1 && fmaxf(fmaxf(b.x, b.y), fmaxf(b.z, b.w)) > T) PUSH4(b, 4 * i1);
        if (h2 && fmaxf(fmaxf(c.x, c.y), fmaxf(c.z, c.w)) > T) PUSH4(c, 4 * i2);
        if (h3 && fmaxf(fmaxf(d.x, d.y), fmaxf(d.z, d.w)) > T) PUSH4(d, 4 * i3);
    }
    __syncthreads();

    // Count + overflow check (warp 0).
    if (wid == 0) {
        int c = s_wcnt[lane];
        int ov = __any_sync(0xffffffffu, c > kWCap) ? 1 : 0;
        int t = c;
#pragma unroll
        for (int o = 16; o > 0; o >>= 1) t += __shfl_xor_sync(0xffffffffu, t, o);
        if (lane == 0) { s_total = t; s_ovf = ov; }
    }
    __syncthreads();
    int total = s_total, ovf = s_ovf;

    // Retry ladder (essentially never taken).
    for (int attempt = 0; attempt < 4 && (total < kTopK || ovf); ++attempt) {
        if (ovf) rank = rank >> 1;                          // raise threshold
        else     rank = (rank < 31) ? (rank * 2 + 1) : 31;  // lower threshold
        __syncthreads();
        if (tid < 32) s_wcnt[tid] = 0;
        if (tid == 0) s_T = s_wm[31 - rank];
        __syncthreads();
        T = s_T;
        for (int i = tid; i < n4; i += kThreads) {
            float4 a = __ldcs(&rin4[i]);
            if (fmaxf(fmaxf(a.x, a.y), fmaxf(a.z, a.w)) > T) PUSH4(a, 4 * i);
        }
        __syncthreads();
        if (wid == 0) {
            int c = s_wcnt[lane];
            int ov = __any_sync(0xffffffffu, c > kWCap) ? 1 : 0;
            int t = c;
#pragma unroll
            for (int o = 16; o > 0; o >>= 1) t += __shfl_xor_sync(0xffffffffu, t, o);
            if (lane == 0) { s_total = t; s_ovf = ov; }
        }
        __syncthreads();
        total = s_total; ovf = s_ovf;
    }
#undef PUSH4

    // ---------------- Phase 1.5: compact per-warp segments into s_sorted ----------------
    if (wid == 0) {
        int c = min(s_wcnt[lane], kWCap);
        // exclusive scan
        int x = c;
#pragma unroll
        for (int o = 1; o < 32; o <<= 1) {
            int y = __shfl_up_sync(0xffffffffu, x, o);
            if (lane >= o) x += y;
        }
        s_woff[lane] = x - c;  // exclusive prefix
    }
    __syncthreads();
    {
        int c   = min(s_wcnt[wid], kWCap);
        int off = s_woff[wid];
        for (int e = lane; e < c; e += 32)
            s_sorted[off + e] = s_cand[wid * kWCap + e];
    }
    __syncthreads();

    // ---------------- Phase 2: bitonic sort (descending) ----------------
    if (total <= kThreads) {
        // Hybrid register bitonic: value lives in a register; j>=32 via shared,
        // j<32 via warp shuffles (no barrier).
        int npad = 64;
        while (npad < total) npad <<= 1;
        const bool act = tid < npad;
        unsigned long long v = 0ull;
        if (act && tid < total) v = s_sorted[tid];

        for (int k = 2; k <= npad; k <<= 1) {
            int j = k >> 1;
            for (; j >= 32; j >>= 1) {
                __syncthreads();
                if (act) s_sorted[tid] = v;
                __syncthreads();
                if (act) {
                    unsigned long long u = s_sorted[tid ^ j];
                    bool takeMax = (((tid & k) == 0) == ((tid & j) == 0));
                    v = takeMax ? (v > u ? v : u) : (v < u ? v : u);
                }
            }
            for (; j > 0; j >>= 1) {
                unsigned long long u = shfl_xor64(v, j);
                bool takeMax = (((tid & k) == 0) == ((tid & j) == 0));
                v = takeMax ? (v > u ? v : u) : (v < u ? v : u);
            }
        }
        __syncthreads();
        if (act) s_sorted[tid] = v;
        __syncthreads();
    } else {
        // Rare fallback (total in (1024, 2048]): shared bitonic over kCap.
        for (int i = total + tid; i < kCap; i += kThreads) s_sorted[i] = 0ull;
        __syncthreads();
        for (int k = 2; k <= kCap; k <<= 1) {
            for (int j = k >> 1; j > 0; j >>= 1) {
#pragma unroll 1
                for (int i = tid; i < kCap; i += kThreads) {
                    int p = i ^ j;
                    if (p > i) {
                        unsigned long long a = s_sorted[i];
                        unsigned long long b = s_sorted[p];
                        bool desc = ((i & k) == 0);
                        if (desc ? (a < b) : (a > b)) { s_sorted[i] = b; s_sorted[p] = a; }
                    }
                }
                __syncthreads();
            }
        }
    }

    // ---------------- Phase 3: softmax cum-prob over top-50 ----------------
    const int lim = (total < kTopK) ? total : kTopK;
    // Parallel exp (warp 0), serial cum scan (thread 0, ~50 adds).
    if (wid == 0) {
        float m = key2f((unsigned)(s_sorted[0] >> 32));
#pragma unroll
        for (int j = lane; j < kTopK; j += 32)
            if (j < lim)
                s_ex[j] = expf(key2f((unsigned)(s_sorted[j] >> 32)) - m);
    }
    __syncthreads();
    if (tid == 0) {
        int kk = 0;
        if (lim > 0) {
            float Z = 0.f;
            for (int j = 0; j < lim; ++j) Z += s_ex[j];
            float invZ = 1.0f / Z;
            float cum = 0.f;
            for (int j = 0; j < lim; ++j) {
                if (j > 0 && cum > kTopP) break;
                kk = j + 1;
                cum += s_ex[j] * invZ;
            }
        }
        s_k = kk;
    }
    __syncthreads();

    // ---------------- Phase 4: scatter kept values over the NEG fill ----------------
    if (tid < s_k) {
        unsigned long long c = s_sorted[tid];
        int idx = (int)(c & 0xFFFFFFFFu);
        rout[idx] = key2f((unsigned)(c >> 32));
    }
}

extern "C" void kernel_launch(void* const* d_in, const int* in_sizes, int n_in,
                              void* d_out, int out_size) {
    const float* in = (const float*)d_in[0];
    float* out = (float*)d_out;
    int rows = in_sizes[0] / kVocab;
    topk_topp_kernel<<<rows, kThreads>>>(in, out);
}